// round 11
// baseline (speedup 1.0000x reference)
#include <cuda_runtime.h>
#include <cuda_bf16.h>

#define BB 16384
#define TT 64

// Ping-pong layer buffers: [B][T][64] (fwd in [0:32), bwd in [32:64))
__device__ float g_buf0[BB * TT * 64];
__device__ float g_buf1[BB * TT * 64];

__device__ __forceinline__ float sigf(float x) {
    return __fdividef(1.0f, 1.0f + __expf(-x));
}
__device__ __forceinline__ float tanh_fast(float x) {
    float e = __expf(-2.0f * x);
    return __fdividef(1.0f - e, 1.0f + e);
}

__device__ __forceinline__ void mma16816(float* c, const unsigned* a,
                                         unsigned b0, unsigned b1) {
    asm volatile(
        "mma.sync.aligned.m16n8k16.row.col.f32.bf16.bf16.f32 "
        "{%0,%1,%2,%3}, {%4,%5,%6,%7}, {%8,%9}, {%0,%1,%2,%3};"
        : "+f"(c[0]), "+f"(c[1]), "+f"(c[2]), "+f"(c[3])
        : "r"(a[0]), "r"(a[1]), "r"(a[2]), "r"(a[3]), "r"(b0), "r"(b1));
}
__device__ __forceinline__ void ldsm4(unsigned* r, unsigned addr) {
    asm volatile(
        "ldmatrix.sync.aligned.m8n8.x4.shared.b16 {%0,%1,%2,%3}, [%4];"
        : "=r"(r[0]), "=r"(r[1]), "=r"(r[2]), "=r"(r[3]) : "r"(addr));
}
__device__ __forceinline__ void ldsm2(unsigned* r, unsigned addr) {
    asm volatile(
        "ldmatrix.sync.aligned.m8n8.x2.shared.b16 {%0,%1}, [%2];"
        : "=r"(r[0]), "=r"(r[1]) : "r"(addr));
}
// 3-pass Markidis accumulate: c += Ahi*Bhi + Ahi*Blo + Alo*Bhi
__device__ __forceinline__ void mma3(float* c, const unsigned* ah, const unsigned* al,
                                     unsigned bh0, unsigned bh1,
                                     unsigned bl0, unsigned bl1) {
    mma16816(c, ah, bh0, bh1);
    mma16816(c, ah, bl0, bl1);
    mma16816(c, al, bh0, bh1);
}
// Split two floats into packed bf16x2 hi / lo residual pairs.
__device__ __forceinline__ void split2(float a, float b, unsigned& hi, unsigned& lo) {
    __nv_bfloat16 ah = __float2bfloat16(a), bh = __float2bfloat16(b);
    __nv_bfloat16 al = __float2bfloat16(a - __bfloat162float(ah));
    __nv_bfloat16 bl = __float2bfloat16(b - __bfloat162float(bh));
    __nv_bfloat162 ph(ah, bh), pl(al, bl);
    hi = *(unsigned*)&ph; lo = *(unsigned*)&pl;
}

#define XELEMS (64 * 72)      // one X buffer (bf16 elems)
#define HELEMS (64 * 40)
#define SMEM_FUSED ((2*XELEMS*2 + 2*96*72 + 2*96*40 + 2*HELEMS*2) * 2)  // bytes

// ---------------------------------------------------------------------------
// Layer 0, tensor-core version (unchanged from round 10).
// ---------------------------------------------------------------------------
#define XSTRIDE 132
#define SMEM_L0 (64 * XSTRIDE * 4 + 2 * 96 * 40 * 2 + 2 * 2 * HELEMS * 2)

__global__ __launch_bounds__(512, 2) void gru_l0_mma(
    const float* __restrict__ x,
    const float* __restrict__ Wih0, const float* __restrict__ Whh0,
    const float* __restrict__ bih0, const float* __restrict__ bhh0)
{
    float* out = g_buf0;
    const int dir = blockIdx.y;
    const size_t b0 = (size_t)blockIdx.x * 64;

    extern __shared__ __align__(16) char sm_raw[];
    float* Xs = (float*)sm_raw;                         // [64][132]
    __nv_bfloat16* Ush = (__nv_bfloat16*)(Xs + 64 * XSTRIDE);  // [96][40]
    __nv_bfloat16* Usl = Ush + 96 * 40;
    __nv_bfloat16* Hh  = Usl + 96 * 40;                 // [2][64][40]
    __nv_bfloat16* Hl  = Hh + 2 * HELEMS;

    const int tid = threadIdx.x;
    const float* Wi = Wih0 + (size_t)dir * 96 * 2;
    const float* Wh = Whh0 + (size_t)dir * 96 * 32;
    const float* bi = bih0 + dir * 96;
    const float* bh = bhh0 + dir * 96;

    for (int q = tid; q < 96 * 8; q += 512) {
        const int gr = q >> 3, k4 = (q & 7) << 2;
        float4 v = *(const float4*)&Wh[gr * 32 + k4];
        unsigned h0, l0, h1, l1;
        split2(v.x, v.y, h0, l0);
        split2(v.z, v.w, h1, l1);
        *(unsigned*)&Ush[gr * 40 + k4]     = h0;
        *(unsigned*)&Ush[gr * 40 + k4 + 2] = h1;
        *(unsigned*)&Usl[gr * 40 + k4]     = l0;
        *(unsigned*)&Usl[gr * 40 + k4 + 2] = l1;
    }
    for (int q = tid; q < 2048; q += 512) {
        const int r = q >> 5, c4 = (q & 31) << 2;
        float4 v = *(const float4*)(x + (b0 + r) * 128 + c4);
        *(float4*)&Xs[r * XSTRIDE + c4] = v;
    }
    for (int q = tid; q < 2 * HELEMS / 2; q += 512) {
        ((unsigned*)Hh)[q] = 0u;
        ((unsigned*)Hl)[q] = 0u;
    }

    const int wid = tid >> 5, lane = tid & 31;
    const int mtile = wid >> 2;
    const int mrow0 = mtile << 4;
    const int ug  = wid & 3;
    const int u0  = ug << 3;
    const int g   = lane >> 2;
    const int t2  = (lane & 3) << 1;
    const int ub  = u0 + t2;

    float bias_r[2], bias_z[2], bias_xn[2], bias_hn[2];
#pragma unroll
    for (int c = 0; c < 2; c++) {
        bias_r[c]  = bi[ub + c]      + bh[ub + c];
        bias_z[c]  = bi[32 + ub + c] + bh[32 + ub + c];
        bias_xn[c] = bi[64 + ub + c];
        bias_hn[c] = bh[64 + ub + c];
    }
    float wxr[2][2], wxz[2][2], wxn[2][2];
#pragma unroll
    for (int c = 0; c < 2; c++) {
        wxr[c][0] = Wi[(ub + c) * 2 + 0];      wxr[c][1] = Wi[(ub + c) * 2 + 1];
        wxz[c][0] = Wi[(32 + ub + c) * 2 + 0]; wxz[c][1] = Wi[(32 + ub + c) * 2 + 1];
        wxn[c][0] = Wi[(64 + ub + c) * 2 + 0]; wxn[c][1] = Wi[(64 + ub + c) * 2 + 1];
    }

    const int a_r = lane & 15, a_k = (lane >> 4) << 3;
    const unsigned hAhi = (unsigned)__cvta_generic_to_shared(&Hh[(mrow0 + a_r) * 40 + a_k]);
    const unsigned hAlo = (unsigned)__cvta_generic_to_shared(&Hl[(mrow0 + a_r) * 40 + a_k]);
    const int b_row = (lane & 7), b_kh = ((lane >> 3) & 1) << 3;
    unsigned uBhi_[3], uBlo_[3];
#pragma unroll
    for (int gt = 0; gt < 3; gt++) {
        const int row = gt * 32 + u0 + b_row;
        uBhi_[gt] = (unsigned)__cvta_generic_to_shared(&Ush[row * 40 + b_kh]);
        uBlo_[gt] = (unsigned)__cvta_generic_to_shared(&Usl[row * 40 + b_kh]);
    }
    const unsigned HBUF = HELEMS * 2;

    __syncthreads();

    float hp[4] = {0.f, 0.f, 0.f, 0.f};
    const int barid = 8 + mtile;
    const float* xsa = Xs + (mrow0 + g) * XSTRIDE;
    const float* xsb = Xs + (mrow0 + g + 8) * XSTRIDE;

    for (int t = 0; t < TT; t++) {
        const int buf = t & 1, nbuf = buf ^ 1;
        const int te = dir ? (TT - 1 - t) : t;

        const float2 xa = *(const float2*)&xsa[te * 2];
        const float2 xb = *(const float2*)&xsb[te * 2];

        float accr[4], accz[4], accxn[4], acchn[4];
        accr[0] = fmaf(xa.y, wxr[0][1], fmaf(xa.x, wxr[0][0], bias_r[0]));
        accr[1] = fmaf(xa.y, wxr[1][1], fmaf(xa.x, wxr[1][0], bias_r[1]));
        accr[2] = fmaf(xb.y, wxr[0][1], fmaf(xb.x, wxr[0][0], bias_r[0]));
        accr[3] = fmaf(xb.y, wxr[1][1], fmaf(xb.x, wxr[1][0], bias_r[1]));
        accz[0] = fmaf(xa.y, wxz[0][1], fmaf(xa.x, wxz[0][0], bias_z[0]));
        accz[1] = fmaf(xa.y, wxz[1][1], fmaf(xa.x, wxz[1][0], bias_z[1]));
        accz[2] = fmaf(xb.y, wxz[0][1], fmaf(xb.x, wxz[0][0], bias_z[0]));
        accz[3] = fmaf(xb.y, wxz[1][1], fmaf(xb.x, wxz[1][0], bias_z[1]));
        accxn[0] = fmaf(xa.y, wxn[0][1], fmaf(xa.x, wxn[0][0], bias_xn[0]));
        accxn[1] = fmaf(xa.y, wxn[1][1], fmaf(xa.x, wxn[1][0], bias_xn[1]));
        accxn[2] = fmaf(xb.y, wxn[0][1], fmaf(xb.x, wxn[0][0], bias_xn[0]));
        accxn[3] = fmaf(xb.y, wxn[1][1], fmaf(xb.x, wxn[1][0], bias_xn[1]));
        acchn[0] = bias_hn[0]; acchn[1] = bias_hn[1];
        acchn[2] = bias_hn[0]; acchn[3] = bias_hn[1];

        const unsigned hoff = buf * HBUF;
#pragma unroll
        for (int ks = 0; ks < 2; ks++) {
            const unsigned ko = ks * 32;
            unsigned ah[4], al[4], bh2[2], bl2[2];
            ldsm4(ah, hAhi + hoff + ko);
            ldsm4(al, hAlo + hoff + ko);
            ldsm2(bh2, uBhi_[0] + ko); ldsm2(bl2, uBlo_[0] + ko);
            mma3(accr, ah, al, bh2[0], bh2[1], bl2[0], bl2[1]);
            ldsm2(bh2, uBhi_[1] + ko); ldsm2(bl2, uBlo_[1] + ko);
            mma3(accz, ah, al, bh2[0], bh2[1], bl2[0], bl2[1]);
            ldsm2(bh2, uBhi_[2] + ko); ldsm2(bl2, uBlo_[2] + ko);
            mma3(acchn, ah, al, bh2[0], bh2[1], bl2[0], bl2[1]);
        }

        float hh[4];
#pragma unroll
        for (int q = 0; q < 4; q++) {
            const float r = sigf(accr[q]);
            const float z = sigf(accz[q]);
            const float n = tanh_fast(fmaf(r, acchn[q], accxn[q]));
            hh[q] = fmaf(z, hp[q] - n, n);
            hp[q] = hh[q];
        }
        unsigned hi01, lo01, hi23, lo23;
        split2(hh[0], hh[1], hi01, lo01);
        split2(hh[2], hh[3], hi23, lo23);
        const int hbo = nbuf * HELEMS;
        *(unsigned*)&Hh[hbo + (mrow0 + g) * 40 + ub]     = hi01;
        *(unsigned*)&Hl[hbo + (mrow0 + g) * 40 + ub]     = lo01;
        *(unsigned*)&Hh[hbo + (mrow0 + g + 8) * 40 + ub] = hi23;
        *(unsigned*)&Hl[hbo + (mrow0 + g + 8) * 40 + ub] = lo23;

        float2 o01; o01.x = hh[0]; o01.y = hh[1];
        float2 o23; o23.x = hh[2]; o23.y = hh[3];
        *(float2*)&out[(b0 + mrow0 + g) * 4096 + (size_t)te * 64 + dir * 32 + ub] = o01;
        *(float2*)&out[(b0 + mrow0 + g + 8) * 4096 + (size_t)te * 64 + dir * 32 + ub] = o23;

        asm volatile("bar.sync %0, %1;" :: "r"(barid), "r"(128) : "memory");
    }
}

// ---------------------------------------------------------------------------
// Fused tensor-core GRU layer (layers 1/2), v3: split r/z accumulator chains.
// hgate accumulates into hr/hz (separate regs) and is issued FIRST after the
// barrier (its ldsm H is the ordered dependency); xgate chains (12 mma) run
// independently. 6 short chains/warp instead of 3x18-deep.
// ---------------------------------------------------------------------------
__global__ __launch_bounds__(512, 2) void gru_fused(
    int phase,
    const float* __restrict__ Wih_l,  // [2][96][64] this layer
    const float* __restrict__ Whh_l,  // [2][96][32]
    const float* __restrict__ bih_l,  // [2][96]
    const float* __restrict__ bhh_l)  // [2][96]
{
    const float* in  = phase ? g_buf1 : g_buf0;
    float*       out = phase ? g_buf0 : g_buf1;
    const int dir = blockIdx.y;
    const size_t b0 = (size_t)blockIdx.x * 64;

    extern __shared__ __align__(16) __nv_bfloat16 sm[];
    __nv_bfloat16* Xhi = sm;                      // [2][64][72]
    __nv_bfloat16* Xlo = Xhi + 2 * XELEMS;
    __nv_bfloat16* Wsh = Xlo + 2 * XELEMS;        // [96][72]
    __nv_bfloat16* Wsl = Wsh + 96 * 72;
    __nv_bfloat16* Ush = Wsl + 96 * 72;           // [96][40]
    __nv_bfloat16* Usl = Ush + 96 * 40;
    __nv_bfloat16* Hh  = Usl + 96 * 40;           // [2][64][40]
    __nv_bfloat16* Hl  = Hh + 2 * HELEMS;

    const int tid = threadIdx.x;
    const float* Wi = Wih_l + (size_t)dir * 96 * 64;
    const float* Wh = Whh_l + (size_t)dir * 96 * 32;
    const float* bi = bih_l + dir * 96;
    const float* bh = bhh_l + dir * 96;

    for (int q = tid; q < 96 * 16; q += 512) {
        const int gr = q >> 4, k4 = (q & 15) << 2;
        float4 v = *(const float4*)&Wi[gr * 64 + k4];
        unsigned h0, l0, h1, l1;
        split2(v.x, v.y, h0, l0);
        split2(v.z, v.w, h1, l1);
        *(unsigned*)&Wsh[gr * 72 + k4]     = h0;
        *(unsigned*)&Wsh[gr * 72 + k4 + 2] = h1;
        *(unsigned*)&Wsl[gr * 72 + k4]     = l0;
        *(unsigned*)&Wsl[gr * 72 + k4 + 2] = l1;
    }
    for (int q = tid; q < 96 * 8; q += 512) {
        const int gr = q >> 3, k4 = (q & 7) << 2;
        float4 v = *(const float4*)&Wh[gr * 32 + k4];
        unsigned h0, l0, h1, l1;
        split2(v.x, v.y, h0, l0);
        split2(v.z, v.w, h1, l1);
        *(unsigned*)&Ush[gr * 40 + k4]     = h0;
        *(unsigned*)&Ush[gr * 40 + k4 + 2] = h1;
        *(unsigned*)&Usl[gr * 40 + k4]     = l0;
        *(unsigned*)&Usl[gr * 40 + k4 + 2] = l1;
    }
    for (int q = tid; q < 2 * HELEMS / 2; q += 512) {
        ((unsigned*)Hh)[q] = 0u;
        ((unsigned*)Hl)[q] = 0u;
    }

    const int wid = tid >> 5, lane = tid & 31;
    const int mtile = wid >> 2;
    const int mrow0 = mtile << 4;
    const int ug  = wid & 3;
    const int u0  = ug << 3;
    const int g   = lane >> 2;
    const int t2  = (lane & 3) << 1;

    const int ub = u0 + t2;
    float bias_r[2], bias_z[2], bias_xn[2], bias_hn[2];
#pragma unroll
    for (int c = 0; c < 2; c++) {
        bias_r[c]  = bi[ub + c]      + bh[ub + c];
        bias_z[c]  = bi[32 + ub + c] + bh[32 + ub + c];
        bias_xn[c] = bi[64 + ub + c];
        bias_hn[c] = bh[64 + ub + c];
    }

    const int a_r = lane & 15, a_k = (lane >> 4) << 3;
    const unsigned xAhi = (unsigned)__cvta_generic_to_shared(&Xhi[(mrow0 + a_r) * 72 + a_k]);
    const unsigned xAlo = (unsigned)__cvta_generic_to_shared(&Xlo[(mrow0 + a_r) * 72 + a_k]);
    const unsigned hAhi = (unsigned)__cvta_generic_to_shared(&Hh[(mrow0 + a_r) * 40 + a_k]);
    const unsigned hAlo = (unsigned)__cvta_generic_to_shared(&Hl[(mrow0 + a_r) * 40 + a_k]);
    const int b_row = (lane & 7), b_kh = ((lane >> 3) & 1) << 3;
    unsigned wBhi_[3], wBlo_[3], uBhi_[3], uBlo_[3];
#pragma unroll
    for (int gt = 0; gt < 3; gt++) {
        const int row = gt * 32 + u0 + b_row;
        wBhi_[gt] = (unsigned)__cvta_generic_to_shared(&Wsh[row * 72 + b_kh]);
        wBlo_[gt] = (unsigned)__cvta_generic_to_shared(&Wsl[row * 72 + b_kh]);
        uBhi_[gt] = (unsigned)__cvta_generic_to_shared(&Ush[row * 40 + b_kh]);
        uBlo_[gt] = (unsigned)__cvta_generic_to_shared(&Usl[row * 40 + b_kh]);
    }
    const unsigned XBUF = XELEMS * 2;
    const unsigned HBUF = HELEMS * 2;

    const int gtid = tid & 127;
    const int xr = mrow0 + (gtid >> 3);
    const int xc = (gtid & 7) << 3;
    const float* xrow = in + (b0 + xr) * 4096 + xc;
    __nv_bfloat16* xdh = Xhi + xr * 72 + xc;
    __nv_bfloat16* xdl = Xlo + xr * 72 + xc;
    float4 px[2];

    auto store_x = [&](int nb) {
        uint4 hv, lv;
        split2(px[0].x, px[0].y, hv.x, lv.x);
        split2(px[0].z, px[0].w, hv.y, lv.y);
        split2(px[1].x, px[1].y, hv.z, lv.z);
        split2(px[1].z, px[1].w, hv.w, lv.w);
        *(uint4*)(xdh + nb * XELEMS) = hv;
        *(uint4*)(xdl + nb * XELEMS) = lv;
    };

    {
        const int te0 = dir ? (TT - 1) : 0;
        px[0] = *(const float4*)(xrow + te0 * 64);
        px[1] = *(const float4*)(xrow + te0 * 64 + 4);
        store_x(0);
        const int te1 = dir ? (TT - 2) : 1;
        px[0] = *(const float4*)(xrow + te1 * 64);
        px[1] = *(const float4*)(xrow + te1 * 64 + 4);
    }
    __syncthreads();

    float hp[4] = {0.f, 0.f, 0.f, 0.f};
    const int barid = 8 + mtile;

    for (int t = 0; t < TT; t++) {
        const int buf = t & 1, nbuf = buf ^ 1;
        const int te = dir ? (TT - 1 - t) : t;

        // Accumulators: xgate chains in accr/accz/accxn, hgate chains in
        // hr/hz/acchn (disjoint registers -> 6 independent mma chains).
        float accr[4], accz[4], accxn[4], acchn[4], hr[4], hz[4];
        accr[0] = bias_r[0];  accr[1] = bias_r[1];
        accr[2] = bias_r[0];  accr[3] = bias_r[1];
        accz[0] = bias_z[0];  accz[1] = bias_z[1];
        accz[2] = bias_z[0];  accz[3] = bias_z[1];
        accxn[0] = bias_xn[0]; accxn[1] = bias_xn[1];
        accxn[2] = bias_xn[0]; accxn[3] = bias_xn[1];
        acchn[0] = bias_hn[0]; acchn[1] = bias_hn[1];
        acchn[2] = bias_hn[0]; acchn[3] = bias_hn[1];
#pragma unroll
        for (int q = 0; q < 4; q++) { hr[q] = 0.f; hz[q] = 0.f; }

        // hgate FIRST: the short, barrier-ordered chains start immediately.
        const unsigned hoff = buf * HBUF;
#pragma unroll
        for (int ks = 0; ks < 2; ks++) {
            const unsigned ko = ks * 32;
            unsigned ah[4], al[4], bh2[2], bl2[2];
            ldsm4(ah, hAhi + hoff + ko);
            ldsm4(al, hAlo + hoff + ko);
            ldsm2(bh2, uBhi_[0] + ko); ldsm2(bl2, uBlo_[0] + ko);
            mma3(hr, ah, al, bh2[0], bh2[1], bl2[0], bl2[1]);
            ldsm2(bh2, uBhi_[1] + ko); ldsm2(bl2, uBlo_[1] + ko);
            mma3(hz, ah, al, bh2[0], bh2[1], bl2[0], bl2[1]);
            ldsm2(bh2, uBhi_[2] + ko); ldsm2(bl2, uBlo_[2] + ko);
            mma3(acchn, ah, al, bh2[0], bh2[1], bl2[0], bl2[1]);
        }

        // xgate: independent 12-deep chains, overlap with hgate via scoreboard.
        const unsigned xoff = buf * XBUF;
#pragma unroll
        for (int ks = 0; ks < 4; ks++) {
            const unsigned ko = ks * 32;
            unsigned ah[4], al[4], bh2[2], bl2[2];
            ldsm4(ah, xAhi + xoff + ko);
            ldsm4(al, xAlo + xoff + ko);
            ldsm2(bh2, wBhi_[0] + ko); ldsm2(bl2, wBlo_[0] + ko);
            mma3(accr, ah, al, bh2[0], bh2[1], bl2[0], bl2[1]);
            ldsm2(bh2, wBhi_[1] + ko); ldsm2(bl2, wBlo_[1] + ko);
            mma3(accz, ah, al, bh2[0], bh2[1], bl2[0], bl2[1]);
            ldsm2(bh2, wBhi_[2] + ko); ldsm2(bl2, wBlo_[2] + ko);
            mma3(accxn, ah, al, bh2[0], bh2[1], bl2[0], bl2[1]);
        }

        // Stage next x while mma drains.
        if (t + 1 < TT) {
            store_x(nbuf);
            if (t + 2 < TT) {
                const int te2 = dir ? (TT - 3 - t) : (t + 2);
                px[0] = *(const float4*)(xrow + te2 * 64);
                px[1] = *(const float4*)(xrow + te2 * 64 + 4);
            }
        }

        float hh[4];
#pragma unroll
        for (int q = 0; q < 4; q++) {
            const float r = sigf(accr[q] + hr[q]);
            const float z = sigf(accz[q] + hz[q]);
            const float n = tanh_fast(fmaf(r, acchn[q], accxn[q]));
            hh[q] = fmaf(z, hp[q] - n, n);
            hp[q] = hh[q];
        }
        unsigned hi01, lo01, hi23, lo23;
        split2(hh[0], hh[1], hi01, lo01);
        split2(hh[2], hh[3], hi23, lo23);
        const int hbo = nbuf * HELEMS;
        *(unsigned*)&Hh[hbo + (mrow0 + g) * 40 + ub]     = hi01;
        *(unsigned*)&Hl[hbo + (mrow0 + g) * 40 + ub]     = lo01;
        *(unsigned*)&Hh[hbo + (mrow0 + g + 8) * 40 + ub] = hi23;
        *(unsigned*)&Hl[hbo + (mrow0 + g + 8) * 40 + ub] = lo23;

        float2 o01; o01.x = hh[0]; o01.y = hh[1];
        float2 o23; o23.x = hh[2]; o23.y = hh[3];
        *(float2*)&out[(b0 + mrow0 + g) * 4096 + (size_t)te * 64 + dir * 32 + ub] = o01;
        *(float2*)&out[(b0 + mrow0 + g + 8) * 4096 + (size_t)te * 64 + dir * 32 + ub] = o23;

        asm volatile("bar.sync %0, %1;" :: "r"(barid), "r"(128) : "memory");
    }
}

// ---------------------------------------------------------------------------
// Final FC: y = tanh(out @ Wfc.T + bfc). Warp per row, shuffle reduction.
// ---------------------------------------------------------------------------
__global__ __launch_bounds__(256) void fc_kernel(
    const float* __restrict__ Wfc, const float* __restrict__ bfc,
    float* __restrict__ outp)
{
    const float* in = g_buf0;  // layer 2 output
    const int lane = threadIdx.x & 31;
    const int warp = (blockIdx.x * blockDim.x + threadIdx.x) >> 5;
    const int nwarps = (gridDim.x * blockDim.x) >> 5;

    const float w0a = __ldg(&Wfc[2 * lane]),      w0b = __ldg(&Wfc[2 * lane + 1]);
    const float w1a = __ldg(&Wfc[64 + 2 * lane]), w1b = __ldg(&Wfc[64 + 2 * lane + 1]);
    const float b0 = __ldg(&bfc[0]), b1 = __ldg(&bfc[1]);

    const int nrows = BB * TT;
    for (int row = warp; row < nrows; row += nwarps) {
        float2 xv = *(const float2*)&in[(size_t)row * 64 + 2 * lane];
        float y0 = fmaf(xv.y, w0b, xv.x * w0a);
        float y1 = fmaf(xv.y, w1b, xv.x * w1a);
#pragma unroll
        for (int o = 16; o > 0; o >>= 1) {
            y0 += __shfl_xor_sync(0xFFFFFFFFu, y0, o);
            y1 += __shfl_xor_sync(0xFFFFFFFFu, y1, o);
        }
        if (lane == 0) {
            float2 r;
            r.x = tanh_fast(y0 + b0);
            r.y = tanh_fast(y1 + b1);
            *(float2*)&outp[(size_t)row * 2] = r;
        }
    }
}

// ---------------------------------------------------------------------------
extern "C" void kernel_launch(void* const* d_in, const int* in_sizes, int n_in,
                              void* d_out, int out_size)
{
    const float* x    = (const float*)d_in[0];
    const float* Wih0 = (const float*)d_in[1];
    const float* Whh0 = (const float*)d_in[2];
    const float* bih0 = (const float*)d_in[3];
    const float* bhh0 = (const float*)d_in[4];
    const float* Wih  = (const float*)d_in[5];
    const float* Whh  = (const float*)d_in[6];
    const float* bih  = (const float*)d_in[7];
    const float* bhh  = (const float*)d_in[8];
    const float* Wfc  = (const float*)d_in[9];
    const float* bfc  = (const float*)d_in[10];
    float* out = (float*)d_out;

    cudaFuncSetAttribute(gru_fused, cudaFuncAttributeMaxDynamicSharedMemorySize,
                         SMEM_FUSED);
    cudaFuncSetAttribute(gru_l0_mma, cudaFuncAttributeMaxDynamicSharedMemorySize,
                         SMEM_L0);

    // Layer 0 -> buf0 (tensor-core)
    gru_l0_mma<<<dim3(BB / 64, 2), 512, SMEM_L0>>>(x, Wih0, Whh0, bih0, bhh0);
    // Layer 1: buf0 -> buf1 (fused)
    gru_fused<<<dim3(BB / 64, 2), 512, SMEM_FUSED>>>(0, Wih, Whh, bih, bhh);
    // Layer 2: buf1 -> buf0 (fused)
    gru_fused<<<dim3(BB / 64, 2), 512, SMEM_FUSED>>>(
        1, Wih + 2 * 96 * 64, Whh + 2 * 96 * 32, bih + 2 * 96, bhh + 2 * 96);
    // FC
    fc_kernel<<<2048, 256>>>(Wfc, bfc, out);
}